// round 5
// baseline (speedup 1.0000x reference)
#include <cuda_runtime.h>
#include <cstdint>

// Compact per-row maps (no clearing needed):
//   g_tok[d*T + rank] = global token id of the rank-th kept token in row d
//   g_idx0/g_total/g_zero: ring start, kept count, special zeroed slot (-1 if none)
#define MAX_D  64
#define MAX_DT (8 * 32768)
__device__ int g_tok[MAX_DT];
__device__ int g_idx0[MAX_D];
__device__ int g_total[MAX_D];
__device__ int g_zero[MAX_D];

__device__ __forceinline__ int mask_at(const void* mask, int mtype, long i) {
    if (mtype == 1) return ((const int*)mask)[i] != 0;          // int32
    if (mtype == 2) return ((const float*)mask)[i] != 0.0f;     // float32
    return ((const uint8_t*)mask)[i] != 0;                      // uint8/bool
}

// One block per cache row d (1024 threads). Detects mask dtype, scans the mask
// row, emits the compact rank->token list and per-row params + tail outputs.
__global__ void setup_kernel(const void* __restrict__ mask,
                             const int* __restrict__ n_valid,
                             const int* __restrict__ index,
                             float* __restrict__ out_tail,
                             int D, int T, int M)
{
    const int d   = blockIdx.x;
    const int tid = threadIdx.x;
    const int NT  = blockDim.x;

    // ---- mask dtype probe over first D*T bytes (valid for all 3 dtypes) ----
    // float32: 1.0f has bytes 0x00 0x00 0x80 0x3f -> some byte > 1
    // int32  : 0/1 little-endian -> nonzero bytes only at pos%4==0
    // uint8  : 0/1 at every position -> nonzero at pos%4!=0 (w.h.p.)
    __shared__ int s_gt1, s_nzmod;
    if (tid == 0) { s_gt1 = 0; s_nzmod = 0; }
    __syncthreads();
    {
        const uint8_t* mb = (const uint8_t*)mask;
        const long nb = (long)D * T;
        int gt1 = 0, nzmod = 0;
        for (long i = tid; i < nb; i += NT) {
            uint8_t b = mb[i];
            if (b > 1) gt1 = 1;
            else if (b != 0 && (i & 3)) nzmod = 1;
        }
        if (gt1)   atomicOr(&s_gt1, 1);
        if (nzmod) atomicOr(&s_nzmod, 1);
    }
    __syncthreads();

    const int mtype = s_gt1 ? 2 : (s_nzmod ? 0 : 1);
    const long mbase = (long)d * T;

    const int chunk = (T + NT - 1) / NT;
    const int start = tid * chunk;

    int cnt = 0;
    for (int j = 0; j < chunk; ++j) {
        int t = start + j;
        if (t < T && mask_at(mask, mtype, mbase + t)) cnt++;
    }

    // Block exclusive scan over per-thread counts.
    const unsigned lane = tid & 31u;
    const unsigned wid  = tid >> 5;
    int v = cnt;
    #pragma unroll
    for (int off = 1; off < 32; off <<= 1) {
        int n = __shfl_up_sync(0xffffffffu, v, off);
        if (lane >= (unsigned)off) v += n;
    }
    __shared__ int warp_tot[32];
    __shared__ int warp_pref[33];
    if (lane == 31) warp_tot[wid] = v;
    __syncthreads();
    if (tid == 0) {
        int s = 0;
        int nw = (NT + 31) >> 5;
        for (int w = 0; w < nw; ++w) { warp_pref[w] = s; s += warp_tot[w]; }
        warp_pref[nw] = s;
    }
    __syncthreads();
    const int excl  = warp_pref[wid] + (v - cnt);
    const int total = warp_pref[(NT + 31) >> 5];

    int rank = excl;
    int* tok = g_tok + (long)d * T;
    for (int j = 0; j < chunk; ++j) {
        int t = start + j;
        if (t < T && mask_at(mask, mtype, mbase + t)) {
            tok[rank++] = d * T + t;          // global token id, in rank order
        }
    }

    if (tid == 0) {
        const int idx0 = index[d];
        g_idx0[d]  = idx0;
        g_total[d] = total;
        // First token masked -> offsets[0] = -1 -> slot (index-1) mod M is
        // set(0)+add(0) by the reference. Never collides with kept slots
        // since total < M.
        int zs = -1;
        if (T > 0 && !mask_at(mask, mtype, mbase) && total < M) {
            zs = idx0 - 1;
            if (zs < 0) zs += M;
        }
        g_zero[d] = zs;
        if (out_tail) {
            long nv = (long)n_valid[d] + total;
            if (nv > M) nv = M;
            out_tail[d]     = (float)nv;                     // new_n_valid
            out_tail[D + d] = (float)((idx0 + total) % M);   // new_index
        }
    }
}

// Grid (ceil(M/8), D): blockIdx.y = cache row d, blockIdx.x covers 8 ring
// slots. No divides on the critical path; per-d params loaded once. 8
// independent LDG.128 issue back-to-back per thread (MLP_p1 = 8). Streaming
// hints: every byte is touched once.
__global__ void write_kernel8(const float4* __restrict__ cache,
                              const float4* __restrict__ acts,
                              float4* __restrict__ out,
                              int DIM4, int M, int T)
{
    const int t  = threadIdx.x;
    const int d  = blockIdx.y;
    const int s0 = blockIdx.x * 8;

    const int idx0  = g_idx0[d];
    const int total = g_total[d];
    const int zslot = g_zero[d];
    const int* tok  = g_tok + (long)d * T;
    const long rowb = (long)d * M + s0;

    if (s0 + 7 < M) {
        const float4* p[8];
        int zo[8];
        #pragma unroll
        for (int i = 0; i < 8; ++i) {
            const int s = s0 + i;
            int rank = s - idx0;
            if (rank < 0) rank += M;
            const bool from_acts = rank < total;
            const int  tk = from_acts ? tok[rank] : 0;
            p[i] = (from_acts ? acts + (long)tk * DIM4
                              : cache + (rowb + i) * DIM4) + t;
            zo[i] = (s == zslot);
        }

        float4 v[8];
        #pragma unroll
        for (int i = 0; i < 8; ++i) v[i] = __ldcs(p[i]);

        const float4 z = make_float4(0.f, 0.f, 0.f, 0.f);
        float4* o = out + rowb * DIM4 + t;
        #pragma unroll
        for (int i = 0; i < 8; ++i) {
            if (zo[i]) v[i] = z;
            __stcs(o + (long)i * DIM4, v[i]);
        }
    } else {
        for (int i = 0; s0 + i < M; ++i) {
            const int s = s0 + i;
            int rank = s - idx0;
            if (rank < 0) rank += M;
            const bool from_acts = rank < total;
            const int  tk = from_acts ? tok[rank] : 0;
            const float4* p = (from_acts ? acts + (long)tk * DIM4
                                         : cache + (rowb + i) * DIM4) + t;
            float4 v = __ldcs(p);
            if (s == zslot) v = make_float4(0.f, 0.f, 0.f, 0.f);
            __stcs(out + (rowb + i) * DIM4 + t, v);
        }
    }
}

extern "C" void kernel_launch(void* const* d_in, const int* in_sizes, int n_in,
                              void* d_out, int out_size)
{
    const float* cache   = (const float*)d_in[0];
    const float* acts    = (const float*)d_in[1];
    const void*  mask    = (const void*)d_in[2];
    const int*   n_valid = (const int*)d_in[3];
    const int*   index   = (const int*)d_in[4];

    const int  D      = in_sizes[3];                      // 8
    const long DT     = (long)in_sizes[2];                // D*T
    const int  T      = (int)(DT / D);                    // 4096
    const int  DIM    = (int)((long)in_sizes[1] / DT);    // 768
    const long cacheN = (long)in_sizes[0];                // D*M*DIM
    const int  M      = (int)(cacheN / ((long)D * DIM));  // 32768
    const int  DIM4   = DIM / 4;

    float* out  = (float*)d_out;
    float* tail = ((long)out_size >= cacheN + 2L * D) ? (out + cacheN) : nullptr;

    setup_kernel<<<D, 1024>>>(mask, n_valid, index, tail, D, T, M);

    dim3 grid((unsigned)((M + 7) / 8), (unsigned)D, 1);
    write_kernel8<<<grid, DIM4>>>((const float4*)cache,
                                  (const float4*)acts,
                                  (float4*)out, DIM4, M, T);
}

// round 6
// speedup vs baseline: 1.0158x; 1.0158x over previous
#include <cuda_runtime.h>
#include <cstdint>

// Compact per-row maps (no clearing needed):
//   g_tok[d*T + rank] = global token id of the rank-th kept token in row d
//   g_idx0/g_total/g_zero: ring start, kept count, special zeroed slot (-1 if none)
#define MAX_D  64
#define MAX_DT (8 * 32768)
__device__ int g_tok[MAX_DT];
__device__ int g_idx0[MAX_D];
__device__ int g_total[MAX_D];
__device__ int g_zero[MAX_D];

__device__ __forceinline__ int mask_at(const void* mask, int mtype, long i) {
    if (mtype == 1) return ((const int*)mask)[i] != 0;          // int32
    if (mtype == 2) return ((const float*)mask)[i] != 0.0f;     // float32
    return ((const uint8_t*)mask)[i] != 0;                      // uint8/bool
}

// One block per cache row d (1024 threads). Detects mask dtype (own row only),
// scans the mask row, emits the compact rank->token list and per-row params +
// tail outputs. Triggers PDL completion so write_kernel8 can start.
__global__ void setup_kernel(const void* __restrict__ mask,
                             const int* __restrict__ n_valid,
                             const int* __restrict__ index,
                             float* __restrict__ out_tail,
                             int D, int T, int M)
{
    const int d   = blockIdx.x;
    const int tid = threadIdx.x;
    const int NT  = blockDim.x;

    // ---- mask dtype probe over this row's T "elements" worth of bytes ----
    // float32: 1.0f has bytes 0x00 0x00 0x80 0x3f -> some byte > 1
    // int32  : 0/1 little-endian -> nonzero bytes only at pos%4==0
    // uint8  : 0/1 at every position -> nonzero at pos%4!=0 (w.h.p.)
    __shared__ int s_gt1, s_nzmod;
    if (tid == 0) { s_gt1 = 0; s_nzmod = 0; }
    __syncthreads();
    {
        // Probe the first T bytes of this row under the *byte* interpretation;
        // for int32/float32 masks this lies inside row d's data for any dtype
        // (d*T bytes <= d*T*4 etc. -> always within the buffer).
        const uint8_t* mb = (const uint8_t*)mask + (long)d * T;
        int gt1 = 0, nzmod = 0;
        for (int i = tid; i < T; i += NT) {
            uint8_t b = mb[i];
            if (b > 1) gt1 = 1;
            else if (b != 0 && (i & 3)) nzmod = 1;
        }
        if (gt1)   atomicOr(&s_gt1, 1);
        if (nzmod) atomicOr(&s_nzmod, 1);
    }
    __syncthreads();

    const int mtype = s_gt1 ? 2 : (s_nzmod ? 0 : 1);
    const long mbase = (long)d * T;

    const int chunk = (T + NT - 1) / NT;
    const int start = tid * chunk;

    int cnt = 0;
    for (int j = 0; j < chunk; ++j) {
        int t = start + j;
        if (t < T && mask_at(mask, mtype, mbase + t)) cnt++;
    }

    // Block exclusive scan over per-thread counts.
    const unsigned lane = tid & 31u;
    const unsigned wid  = tid >> 5;
    int v = cnt;
    #pragma unroll
    for (int off = 1; off < 32; off <<= 1) {
        int n = __shfl_up_sync(0xffffffffu, v, off);
        if (lane >= (unsigned)off) v += n;
    }
    __shared__ int warp_tot[32];
    __shared__ int warp_pref[33];
    if (lane == 31) warp_tot[wid] = v;
    __syncthreads();
    if (tid == 0) {
        int s = 0;
        int nw = (NT + 31) >> 5;
        for (int w = 0; w < nw; ++w) { warp_pref[w] = s; s += warp_tot[w]; }
        warp_pref[nw] = s;
    }
    __syncthreads();
    const int excl  = warp_pref[wid] + (v - cnt);
    const int total = warp_pref[(NT + 31) >> 5];

    int rank = excl;
    int* tok = g_tok + (long)d * T;
    for (int j = 0; j < chunk; ++j) {
        int t = start + j;
        if (t < T && mask_at(mask, mtype, mbase + t)) {
            tok[rank++] = d * T + t;          // global token id, in rank order
        }
    }

    if (tid == 0) {
        const int idx0 = index[d];
        g_idx0[d]  = idx0;
        g_total[d] = total;
        // First token masked -> offsets[0] = -1 -> slot (index-1) mod M is
        // set(0)+add(0) by the reference. Never collides with kept slots
        // since total < M.
        int zs = -1;
        if (T > 0 && !mask_at(mask, mtype, mbase) && total < M) {
            zs = idx0 - 1;
            if (zs < 0) zs += M;
        }
        g_zero[d] = zs;
        if (out_tail) {
            long nv = (long)n_valid[d] + total;
            if (nv > M) nv = M;
            out_tail[d]     = (float)nv;                     // new_n_valid
            out_tail[D + d] = (float)((idx0 + total) % M);   // new_index
        }
    }

    // Make g_* globally visible, then allow the dependent launch to proceed.
    __syncthreads();
    __threadfence();
    cudaTriggerProgrammaticLaunchCompletion();
}

// Grid (ceil(M/8), D): blockIdx.y = cache row d, blockIdx.x covers 8 ring
// slots. Per-d params loaded once; 8 independent LDG.128 per thread
// (MLP_p1 = 8). Streaming hints: every byte is touched once. PDL: waits for
// setup_kernel's trigger before reading g_*.
__global__ void write_kernel8(const float4* __restrict__ cache,
                              const float4* __restrict__ acts,
                              float4* __restrict__ out,
                              int DIM4, int M, int T)
{
    const int t  = threadIdx.x;
    const int d  = blockIdx.y;
    const int s0 = blockIdx.x * 8;

    cudaGridDependencySynchronize();

    const int idx0  = g_idx0[d];
    const int total = g_total[d];
    const int zslot = g_zero[d];
    const int* tok  = g_tok + (long)d * T;
    const long rowb = (long)d * M + s0;

    if (s0 + 7 < M) {
        const float4* p[8];
        int zo[8];
        #pragma unroll
        for (int i = 0; i < 8; ++i) {
            const int s = s0 + i;
            int rank = s - idx0;
            if (rank < 0) rank += M;
            const bool from_acts = rank < total;
            const int  tk = from_acts ? tok[rank] : 0;
            p[i] = (from_acts ? acts + (long)tk * DIM4
                              : cache + (rowb + i) * DIM4) + t;
            zo[i] = (s == zslot);
        }

        float4 v[8];
        #pragma unroll
        for (int i = 0; i < 8; ++i) v[i] = __ldcs(p[i]);

        const float4 z = make_float4(0.f, 0.f, 0.f, 0.f);
        float4* o = out + rowb * DIM4 + t;
        #pragma unroll
        for (int i = 0; i < 8; ++i) {
            if (zo[i]) v[i] = z;
            __stcs(o + (long)i * DIM4, v[i]);
        }
    } else {
        for (int i = 0; s0 + i < M; ++i) {
            const int s = s0 + i;
            int rank = s - idx0;
            if (rank < 0) rank += M;
            const bool from_acts = rank < total;
            const int  tk = from_acts ? tok[rank] : 0;
            const float4* p = (from_acts ? acts + (long)tk * DIM4
                                         : cache + (rowb + i) * DIM4) + t;
            float4 v = __ldcs(p);
            if (s == zslot) v = make_float4(0.f, 0.f, 0.f, 0.f);
            __stcs(out + (rowb + i) * DIM4 + t, v);
        }
    }
}

extern "C" void kernel_launch(void* const* d_in, const int* in_sizes, int n_in,
                              void* d_out, int out_size)
{
    const float* cache   = (const float*)d_in[0];
    const float* acts    = (const float*)d_in[1];
    const void*  mask    = (const void*)d_in[2];
    const int*   n_valid = (const int*)d_in[3];
    const int*   index   = (const int*)d_in[4];

    const int  D      = in_sizes[3];                      // 8
    const long DT     = (long)in_sizes[2];                // D*T
    const int  T      = (int)(DT / D);                    // 4096
    const int  DIM    = (int)((long)in_sizes[1] / DT);    // 768
    const long cacheN = (long)in_sizes[0];                // D*M*DIM
    const int  M      = (int)(cacheN / ((long)D * DIM));  // 32768
    const int  DIM4   = DIM / 4;

    float* out  = (float*)d_out;
    float* tail = ((long)out_size >= cacheN + 2L * D) ? (out + cacheN) : nullptr;

    setup_kernel<<<D, 1024>>>(mask, n_valid, index, tail, D, T, M);

    // Write kernel launched with programmatic stream serialization: it may
    // begin (prologue, block rasterization) while setup is still running and
    // synchronizes on setup's trigger before reading g_*.
    {
        const float4* c4 = (const float4*)cache;
        const float4* a4 = (const float4*)acts;
        float4*       o4 = (float4*)out;

        cudaLaunchConfig_t cfg = {};
        cfg.gridDim  = dim3((unsigned)((M + 7) / 8), (unsigned)D, 1);
        cfg.blockDim = dim3((unsigned)DIM4, 1, 1);
        cfg.dynamicSmemBytes = 0;
        cfg.stream = 0;

        cudaLaunchAttribute attr[1];
        attr[0].id = cudaLaunchAttributeProgrammaticStreamSerialization;
        attr[0].val.programmaticStreamSerializationAllowed = 1;
        cfg.attrs = attr;
        cfg.numAttrs = 1;

        cudaLaunchKernelEx(&cfg, write_kernel8, c4, a4, o4, DIM4, M, T);
    }
}

// round 7
// speedup vs baseline: 1.0179x; 1.0020x over previous
#include <cuda_runtime.h>
#include <cstdint>

// Compact per-row maps (no clearing needed):
//   g_tok[d*T + rank] = global token id of the rank-th kept token in row d
//   g_total/g_zero: kept count, special zeroed slot (-1 if none)
#define MAX_D  64
#define MAX_DT (8 * 32768)
__device__ int g_tok[MAX_DT];
__device__ int g_total[MAX_D];
__device__ int g_zero[MAX_D];

__device__ __forceinline__ int mask_at(const void* mask, int mtype, long i) {
    if (mtype == 1) return ((const int*)mask)[i] != 0;          // int32
    if (mtype == 2) return ((const float*)mask)[i] != 0.0f;     // float32
    return ((const uint8_t*)mask)[i] != 0;                      // uint8/bool
}

// One block per cache row d (1024 threads). Detects mask dtype (own row's
// bytes), scans the mask row, emits the compact rank->token list and per-row
// params + tail outputs. Triggers PDL completion so dependent write blocks
// can proceed.
__global__ void setup_kernel(const void* __restrict__ mask,
                             const int* __restrict__ n_valid,
                             const int* __restrict__ index,
                             float* __restrict__ out_tail,
                             int D, int T, int M)
{
    const int d   = blockIdx.x;
    const int tid = threadIdx.x;
    const int NT  = blockDim.x;

    // ---- mask dtype probe over this row's first T bytes ----
    // float32: 1.0f has bytes 0x00 0x00 0x80 0x3f -> some byte > 1
    // int32  : 0/1 little-endian -> nonzero bytes only at pos%4==0
    // uint8  : 0/1 at every position -> nonzero at pos%4!=0 (w.h.p.)
    __shared__ int s_gt1, s_nzmod;
    if (tid == 0) { s_gt1 = 0; s_nzmod = 0; }
    __syncthreads();
    {
        const uint8_t* mb = (const uint8_t*)mask + (long)d * T;
        int gt1 = 0, nzmod = 0;
        for (int i = tid; i < T; i += NT) {
            uint8_t b = mb[i];
            if (b > 1) gt1 = 1;
            else if (b != 0 && (i & 3)) nzmod = 1;
        }
        if (gt1)   atomicOr(&s_gt1, 1);
        if (nzmod) atomicOr(&s_nzmod, 1);
    }
    __syncthreads();

    const int mtype = s_gt1 ? 2 : (s_nzmod ? 0 : 1);
    const long mbase = (long)d * T;

    const int chunk = (T + NT - 1) / NT;
    const int start = tid * chunk;

    int cnt = 0;
    for (int j = 0; j < chunk; ++j) {
        int t = start + j;
        if (t < T && mask_at(mask, mtype, mbase + t)) cnt++;
    }

    // Block exclusive scan over per-thread counts.
    const unsigned lane = tid & 31u;
    const unsigned wid  = tid >> 5;
    int v = cnt;
    #pragma unroll
    for (int off = 1; off < 32; off <<= 1) {
        int n = __shfl_up_sync(0xffffffffu, v, off);
        if (lane >= (unsigned)off) v += n;
    }
    __shared__ int warp_tot[32];
    __shared__ int warp_pref[33];
    if (lane == 31) warp_tot[wid] = v;
    __syncthreads();
    if (tid == 0) {
        int s = 0;
        int nw = (NT + 31) >> 5;
        for (int w = 0; w < nw; ++w) { warp_pref[w] = s; s += warp_tot[w]; }
        warp_pref[nw] = s;
    }
    __syncthreads();
    const int excl  = warp_pref[wid] + (v - cnt);
    const int total = warp_pref[(NT + 31) >> 5];

    int rank = excl;
    int* tok = g_tok + (long)d * T;
    for (int j = 0; j < chunk; ++j) {
        int t = start + j;
        if (t < T && mask_at(mask, mtype, mbase + t)) {
            tok[rank++] = d * T + t;          // global token id, in rank order
        }
    }

    if (tid == 0) {
        const int idx0 = index[d];
        g_total[d] = total;
        // First token masked -> offsets[0] = -1 -> slot (index-1) mod M is
        // set(0)+add(0) by the reference. Never collides with kept slots
        // since total < M.
        int zs = -1;
        if (T > 0 && !mask_at(mask, mtype, mbase) && total < M) {
            zs = idx0 - 1;
            if (zs < 0) zs += M;
        }
        g_zero[d] = zs;
        if (out_tail) {
            long nv = (long)n_valid[d] + total;
            if (nv > M) nv = M;
            out_tail[d]     = (float)nv;                     // new_n_valid
            out_tail[D + d] = (float)((idx0 + total) % M);   // new_index
        }
    }

    // Make g_* globally visible, then allow dependent blocks to proceed.
    __syncthreads();
    __threadfence();
    cudaTriggerProgrammaticLaunchCompletion();
}

// Grid (ceil(M/8), D). idx0 comes straight from the raw `index` input, so a
// block only synchronizes on setup's PDL trigger if one of its 8 ring slots
// can be acts-sourced (rank < T) or can be the zeroed slot (rank == M-1).
// ~87.5% of blocks take the no-sync fast path and stream cache->out while
// setup is still running. 8 independent LDG.128 per thread (MLP_p1 = 8),
// streaming hints (every byte touched once).
__global__ void write_kernel8(const float4* __restrict__ cache,
                              const float4* __restrict__ acts,
                              const int* __restrict__ index,
                              float4* __restrict__ out,
                              int DIM4, int M, int T)
{
    const int t  = threadIdx.x;
    const int d  = blockIdx.y;
    const int s0 = blockIdx.x * 8;

    if (s0 + 7 < M) {
        const int idx0 = index[d];           // raw input: no setup dependency
        int rank0 = s0 - idx0;
        if (rank0 < 0) rank0 += M;
        // Ranks covered by this block: rank0..rank0+7 (mod M).
        const bool needs_sync = (rank0 < T) || (rank0 >= M - 8);

        if (!needs_sync) {
            // Pure cache -> out copy; independent of setup results.
            const long rowb = (long)d * M + s0;
            const float4* c = cache + rowb * DIM4 + t;
            float4 v[8];
            #pragma unroll
            for (int i = 0; i < 8; ++i) v[i] = __ldcs(c + (long)i * DIM4);
            float4* o = out + rowb * DIM4 + t;
            #pragma unroll
            for (int i = 0; i < 8; ++i) __stcs(o + (long)i * DIM4, v[i]);
            return;
        }

        cudaGridDependencySynchronize();

        const int total = g_total[d];
        const int zslot = g_zero[d];
        const int* tok  = g_tok + (long)d * T;
        const long rowb = (long)d * M + s0;

        const float4* p[8];
        int zo[8];
        #pragma unroll
        for (int i = 0; i < 8; ++i) {
            const int s = s0 + i;
            int rank = s - idx0;
            if (rank < 0) rank += M;
            const bool from_acts = rank < total;
            const int  tk = from_acts ? tok[rank] : 0;
            p[i] = (from_acts ? acts + (long)tk * DIM4
                              : cache + (rowb + i) * DIM4) + t;
            zo[i] = (s == zslot);
        }

        float4 v[8];
        #pragma unroll
        for (int i = 0; i < 8; ++i) v[i] = __ldcs(p[i]);

        const float4 z = make_float4(0.f, 0.f, 0.f, 0.f);
        float4* o = out + rowb * DIM4 + t;
        #pragma unroll
        for (int i = 0; i < 8; ++i) {
            if (zo[i]) v[i] = z;
            __stcs(o + (long)i * DIM4, v[i]);
        }
    } else {
        // Tail (M not divisible by 8): always sync, scalar path.
        cudaGridDependencySynchronize();
        const int idx0  = index[d];
        const int total = g_total[d];
        const int zslot = g_zero[d];
        const int* tok  = g_tok + (long)d * T;
        for (int i = 0; s0 + i < M; ++i) {
            const int s = s0 + i;
            int rank = s - idx0;
            if (rank < 0) rank += M;
            const bool from_acts = rank < total;
            const int  tk = from_acts ? tok[rank] : 0;
            const long r = (long)d * M + s;
            const float4* p = (from_acts ? acts + (long)tk * DIM4
                                         : cache + r * DIM4) + t;
            float4 v = __ldcs(p);
            if (s == zslot) v = make_float4(0.f, 0.f, 0.f, 0.f);
            __stcs(out + r * DIM4 + t, v);
        }
    }
}

extern "C" void kernel_launch(void* const* d_in, const int* in_sizes, int n_in,
                              void* d_out, int out_size)
{
    const float* cache   = (const float*)d_in[0];
    const float* acts    = (const float*)d_in[1];
    const void*  mask    = (const void*)d_in[2];
    const int*   n_valid = (const int*)d_in[3];
    const int*   index   = (const int*)d_in[4];

    const int  D      = in_sizes[3];                      // 8
    const long DT     = (long)in_sizes[2];                // D*T
    const int  T      = (int)(DT / D);                    // 4096
    const int  DIM    = (int)((long)in_sizes[1] / DT);    // 768
    const long cacheN = (long)in_sizes[0];                // D*M*DIM
    const int  M      = (int)(cacheN / ((long)D * DIM));  // 32768
    const int  DIM4   = DIM / 4;

    float* out  = (float*)d_out;
    float* tail = ((long)out_size >= cacheN + 2L * D) ? (out + cacheN) : nullptr;

    setup_kernel<<<D, 1024>>>(mask, n_valid, index, tail, D, T, M);

    // PDL: write blocks launch while setup runs; only rank-window blocks wait
    // on the trigger, everyone else streams immediately.
    {
        const float4* c4 = (const float4*)cache;
        const float4* a4 = (const float4*)acts;
        float4*       o4 = (float4*)out;

        cudaLaunchConfig_t cfg = {};
        cfg.gridDim  = dim3((unsigned)((M + 7) / 8), (unsigned)D, 1);
        cfg.blockDim = dim3((unsigned)DIM4, 1, 1);
        cfg.dynamicSmemBytes = 0;
        cfg.stream = 0;

        cudaLaunchAttribute attr[1];
        attr[0].id = cudaLaunchAttributeProgrammaticStreamSerialization;
        attr[0].val.programmaticStreamSerializationAllowed = 1;
        cfg.attrs = attr;
        cfg.numAttrs = 1;

        cudaLaunchKernelEx(&cfg, write_kernel8, c4, a4, index, o4, DIM4, M, T);
    }
}

// round 8
// speedup vs baseline: 1.0186x; 1.0007x over previous
#include <cuda_runtime.h>
#include <cstdint>

// Compact per-row maps (no clearing needed):
//   g_tok[d*T + rank] = global token id of the rank-th kept token in row d
//   g_total/g_zero: kept count, special zeroed slot (-1 if none)
#define MAX_D  64
#define MAX_DT (8 * 32768)
__device__ int g_tok[MAX_DT];
__device__ int g_total[MAX_D];
__device__ int g_zero[MAX_D];
__device__ volatile int g_ready[MAX_D];   // 0 at process start; reset each launch
__device__ unsigned g_done;               // finished-block counter, reset each launch

__device__ __forceinline__ int mask_at(const void* mask, int mtype, long i) {
    if (mtype == 1) return ((const int*)mask)[i] != 0;          // int32
    if (mtype == 2) return ((const float*)mask)[i] != 0.0f;     // float32
    return ((const uint8_t*)mask)[i] != 0;                      // uint8/bool
}

// Single fused kernel. Grid (nb_per_d + 1, D), blockDim = DIM/4.
//  blockIdx.x == 0  : setup for row d (mask scan -> g_tok/g_total/g_zero,
//                     tail outputs), then sets g_ready[d].
//  blockIdx.x == x+1: covers ring ranks T+8x .. T+8x+7 (mod M) of row d.
//    ranks in [T, M-2]  -> pure cache->out copy, no dependency on setup.
//    ranks wrapping / M-1 -> need g_* ; these have the HIGHEST x, so they are
//    scheduled thousands of blocks after setup block x=0 of the same row and
//    the spin-wait never engages in practice.
__global__ void fused_kernel(const float4* __restrict__ cache,
                             const float4* __restrict__ acts,
                             const void*  __restrict__ mask,
                             const int*   __restrict__ n_valid,
                             const int*   __restrict__ index,
                             float4* __restrict__ out,
                             float*  __restrict__ out_tail,
                             int D, int T, int M)
{
    const int t  = threadIdx.x;
    const int NT = blockDim.x;       // = DIM/4
    const int d  = blockIdx.y;

    if (blockIdx.x == 0) {
        // ------------------------- setup for row d -------------------------
        // mask dtype probe over this row's first T bytes:
        // float32: 1.0f bytes 00 00 80 3f -> some byte > 1
        // int32  : nonzero bytes only at pos%4==0
        // uint8  : nonzero at pos%4!=0 (w.h.p.)
        __shared__ int s_gt1, s_nzmod;
        if (t == 0) { s_gt1 = 0; s_nzmod = 0; }
        __syncthreads();
        {
            const uint8_t* mb = (const uint8_t*)mask + (long)d * T;
            int gt1 = 0, nzmod = 0;
            for (int i = t; i < T; i += NT) {
                uint8_t b = mb[i];
                if (b > 1) gt1 = 1;
                else if (b != 0 && (i & 3)) nzmod = 1;
            }
            if (gt1)   atomicOr(&s_gt1, 1);
            if (nzmod) atomicOr(&s_nzmod, 1);
        }
        __syncthreads();

        const int mtype = s_gt1 ? 2 : (s_nzmod ? 0 : 1);
        const long mbase = (long)d * T;

        const int chunk = (T + NT - 1) / NT;
        const int start = t * chunk;

        int cnt = 0;
        for (int j = 0; j < chunk; ++j) {
            int tt = start + j;
            if (tt < T && mask_at(mask, mtype, mbase + tt)) cnt++;
        }

        // Block exclusive scan over per-thread counts.
        const unsigned lane = t & 31u;
        const unsigned wid  = t >> 5;
        int v = cnt;
        #pragma unroll
        for (int off = 1; off < 32; off <<= 1) {
            int n = __shfl_up_sync(0xffffffffu, v, off);
            if (lane >= (unsigned)off) v += n;
        }
        __shared__ int warp_tot[32];
        __shared__ int warp_pref[33];
        if (lane == 31) warp_tot[wid] = v;
        __syncthreads();
        if (t == 0) {
            int s = 0;
            int nw = (NT + 31) >> 5;
            for (int w = 0; w < nw; ++w) { warp_pref[w] = s; s += warp_tot[w]; }
            warp_pref[nw] = s;
        }
        __syncthreads();
        const int excl  = warp_pref[wid] + (v - cnt);
        const int total = warp_pref[(NT + 31) >> 5];

        int rank = excl;
        int* tok = g_tok + (long)d * T;
        for (int j = 0; j < chunk; ++j) {
            int tt = start + j;
            if (tt < T && mask_at(mask, mtype, mbase + tt)) {
                tok[rank++] = d * T + tt;      // global token id, in rank order
            }
        }

        if (t == 0) {
            const int idx0 = index[d];
            g_total[d] = total;
            // First token masked -> offsets[0] = -1 -> slot (index-1) mod M
            // is set(0)+add(0). Never collides with kept slots (total < M).
            int zs = -1;
            if (T > 0 && !mask_at(mask, mtype, mbase) && total < M) {
                zs = idx0 - 1;
                if (zs < 0) zs += M;
            }
            g_zero[d] = zs;
            if (out_tail) {
                long nv = (long)n_valid[d] + total;
                if (nv > M) nv = M;
                out_tail[d]     = (float)nv;                     // new_n_valid
                out_tail[D + d] = (float)((idx0 + total) % M);   // new_index
            }
        }

        __syncthreads();
        __threadfence();                 // publish g_* before the flag
        if (t == 0) g_ready[d] = 1;
    } else {
        // ------------------------- write block -------------------------
        const int x    = blockIdx.x - 1;
        const int k0   = x * 8;                 // first rank offset (rank = T + k)
        const int idx0 = index[d];              // raw input: no setup dependency
        const long rowd = (long)d * M;

        if (k0 + 7 < M) {
            const int rk = T + k0;              // pre-mod rank of i=0
            const bool needs_sync = (rk + 7 >= M - 1);

            if (!needs_sync) {
                // ranks in [T, M-2]: pure cache -> out, slots = (idx0+rank)%M
                long r[8];
                #pragma unroll
                for (int i = 0; i < 8; ++i) {
                    int s = idx0 + rk + i;      // < 2M-2: one subtract suffices
                    if (s >= M) s -= M;
                    r[i] = rowd + s;
                }
                float4 v[8];
                #pragma unroll
                for (int i = 0; i < 8; ++i) v[i] = __ldcs(cache + r[i] * NT + t);
                #pragma unroll
                for (int i = 0; i < 8; ++i) __stcs(out + r[i] * NT + t, v[i]);
            } else {
                if (t == 0) { while (g_ready[d] == 0) __nanosleep(64); }
                __syncthreads();
                __threadfence();                // order g_* reads after flag

                const int total = g_total[d];
                const int zslot = g_zero[d];
                const int* tok  = g_tok + (long)d * T;

                const float4* p[8];
                long ro[8];
                int zo[8];
                #pragma unroll
                for (int i = 0; i < 8; ++i) {
                    int rank = rk + i; if (rank >= M) rank -= M;
                    int s = idx0 + rank; if (s >= M) s -= M;
                    ro[i] = rowd + s;
                    const bool fa = rank < total;
                    const int  tk = fa ? tok[rank] : 0;
                    p[i] = (fa ? acts + (long)tk * NT : cache + ro[i] * NT) + t;
                    zo[i] = (s == zslot);
                }
                float4 v[8];
                #pragma unroll
                for (int i = 0; i < 8; ++i) v[i] = __ldcs(p[i]);
                const float4 z = make_float4(0.f, 0.f, 0.f, 0.f);
                #pragma unroll
                for (int i = 0; i < 8; ++i) {
                    if (zo[i]) v[i] = z;
                    __stcs(out + ro[i] * NT + t, v[i]);
                }
            }
        } else {
            // tail (M not divisible by 8): always sync, scalar path
            if (t == 0) { while (g_ready[d] == 0) __nanosleep(64); }
            __syncthreads();
            __threadfence();
            const int total = g_total[d];
            const int zslot = g_zero[d];
            const int* tok  = g_tok + (long)d * T;
            for (int i = 0; k0 + i < M; ++i) {
                int rank = T + k0 + i; if (rank >= M) rank -= M;
                int s = idx0 + rank; if (s >= M) s -= M;
                const long r = rowd + s;
                const bool fa = rank < total;
                const int  tk = fa ? tok[rank] : 0;
                const float4* p = (fa ? acts + (long)tk * NT : cache + r * NT) + t;
                float4 v = __ldcs(p);
                if (s == zslot) v = make_float4(0.f, 0.f, 0.f, 0.f);
                __stcs(out + r * NT + t, v);
            }
        }
    }

    // -------- launch-epilogue: last finished block resets the flags --------
    if (t == 0) {
        const unsigned nb = gridDim.x * gridDim.y;
        const unsigned v = atomicAdd(&g_done, 1u);
        if (v == nb - 1u) {
            for (int i = 0; i < D && i < MAX_D; ++i) g_ready[i] = 0;
            __threadfence();
            g_done = 0;
        }
    }
}

extern "C" void kernel_launch(void* const* d_in, const int* in_sizes, int n_in,
                              void* d_out, int out_size)
{
    const float* cache   = (const float*)d_in[0];
    const float* acts    = (const float*)d_in[1];
    const void*  mask    = (const void*)d_in[2];
    const int*   n_valid = (const int*)d_in[3];
    const int*   index   = (const int*)d_in[4];

    const int  D      = in_sizes[3];                      // 8
    const long DT     = (long)in_sizes[2];                // D*T
    const int  T      = (int)(DT / D);                    // 4096
    const int  DIM    = (int)((long)in_sizes[1] / DT);    // 768
    const long cacheN = (long)in_sizes[0];                // D*M*DIM
    const int  M      = (int)(cacheN / ((long)D * DIM));  // 32768
    const int  DIM4   = DIM / 4;

    float* out  = (float*)d_out;
    float* tail = ((long)out_size >= cacheN + 2L * D) ? (out + cacheN) : nullptr;

    const int nb_per_d = (M + 7) / 8;
    dim3 grid((unsigned)(nb_per_d + 1), (unsigned)D, 1);
    fused_kernel<<<grid, DIM4>>>((const float4*)cache,
                                 (const float4*)acts,
                                 mask, n_valid, index,
                                 (float4*)out, tail, D, T, M);
}